// round 14
// baseline (speedup 1.0000x reference)
#include <cuda_runtime.h>
#include <cuda_fp16.h>
#include <cstdint>

#define Nn 50000
#define Ee 800000
#define Fd 128          // feature dim = H*OUT = 128
#define NH 2            // heads
#define NB_SCAN 49      // ceil(Nn/1024)

// ---------------- scratch (no allocations allowed) ----------------
__device__ __half g_f0[(size_t)Nn * Fd];  // projected feats (fp16), relation 0
__device__ __half g_f1[(size_t)Nn * Fd];  // projected feats (fp16), relation 1
__device__ float  g_h1[(size_t)Nn * Fd];  // layer-1 output
__device__ float  g_el0[(size_t)Nn * NH];
__device__ float  g_er0[(size_t)Nn * NH];
__device__ float  g_el1[(size_t)Nn * NH];
__device__ float  g_er1[(size_t)Nn * NH];
__device__ int    g_ptr[4][Nn];           // per-graph EXCLUSIVE rowptr starts
__device__ int    g_csr[4][Ee];           // per-graph src ids grouped by dst
__device__ int    g_rank[4][Ee];          // within-bucket rank per edge
__device__ int    g_part[4 * 64];         // scan block partials

// ---------------- packed f32x2 helpers (Blackwell FFMA2 path) ----------------
__device__ __forceinline__ unsigned long long pack2(float lo, float hi) {
    unsigned long long r;
    asm("mov.b64 %0, {%1, %2};" : "=l"(r) : "f"(lo), "f"(hi));
    return r;
}
__device__ __forceinline__ void fma2(unsigned long long& d, unsigned long long a,
                                     unsigned long long b) {
    asm("fma.rn.f32x2 %0, %1, %2, %0;" : "+l"(d) : "l"(a), "l"(b));
}
__device__ __forceinline__ float2 unpack2(unsigned long long v) {
    float2 r;
    asm("mov.b64 {%0, %1}, %2;" : "=f"(r.x), "=f"(r.y) : "l"(v));
    return r;
}

// ---------------- GEMM + fused scores: both relations in one launch ----------
#define GEMM_SMEM (128 * 132 * 4 + 128 * 128 * 4)

__global__ void __launch_bounds__(256) gemm_scores_k(
    const float* __restrict__ A, const float* __restrict__ W,
    const float* __restrict__ al, const float* __restrict__ ar,
    __half* __restrict__ fo0, __half* __restrict__ fo1,
    float* __restrict__ el0, float* __restrict__ er0,
    float* __restrict__ el1, float* __restrict__ er1, int nrows) {
    extern __shared__ float sm[];
    float* As = sm;               // [128][132] padded
    float* Bs = sm + 128 * 132;   // [128][128]
    const int r = blockIdx.y;
    const float* B = W + (size_t)r * Fd * Fd;
    __half* fout = r ? fo1 : fo0;
    float* el = r ? el1 : el0;
    float* er = r ? er1 : er0;
    const float* alr = al + r * Fd;
    const float* arr = ar + r * Fd;
    const int m0 = blockIdx.x * 128;
    const int tid = threadIdx.x;

#pragma unroll
    for (int it = 0; it < 16; it++) {
        int idx = tid + it * 256;       // float4 index, 0..4095
        int row = idx >> 5;
        int c4 = (idx & 31) << 2;
        float4 va = make_float4(0.f, 0.f, 0.f, 0.f);
        if (m0 + row < nrows) va = *(const float4*)&A[(size_t)(m0 + row) * Fd + c4];
        *(float4*)&As[row * 132 + c4] = va;
        *(float4*)&Bs[row * 128 + c4] = *(const float4*)&B[row * Fd + c4];
    }
    __syncthreads();

    const int ty = tid >> 4;   // rows ty*8..ty*8+7
    const int tx = tid & 15;   // cols tx*4 (head0) and 64+tx*4 (head1)

    unsigned long long acc[8][4];
#pragma unroll
    for (int i = 0; i < 8; i++)
#pragma unroll
        for (int j = 0; j < 4; j++) acc[i][j] = 0ull;

#pragma unroll 4
    for (int k = 0; k < 128; k++) {
        float4 b0 = *(const float4*)&Bs[k * 128 + tx * 4];
        float4 b1 = *(const float4*)&Bs[k * 128 + 64 + tx * 4];
        unsigned long long bp0 = pack2(b0.x, b0.y);
        unsigned long long bp1 = pack2(b0.z, b0.w);
        unsigned long long bp2 = pack2(b1.x, b1.y);
        unsigned long long bp3 = pack2(b1.z, b1.w);
#pragma unroll
        for (int i = 0; i < 8; i++) {
            float a = As[(ty * 8 + i) * 132 + k];
            unsigned long long ap = pack2(a, a);
            fma2(acc[i][0], ap, bp0);
            fma2(acc[i][1], ap, bp1);
            fma2(acc[i][2], ap, bp2);
            fma2(acc[i][3], ap, bp3);
        }
    }

    float4 alv0 = __ldg((const float4*)&alr[tx * 4]);
    float4 alv1 = __ldg((const float4*)&alr[64 + tx * 4]);
    float4 arv0 = __ldg((const float4*)&arr[tx * 4]);
    float4 arv1 = __ldg((const float4*)&arr[64 + tx * 4]);

#pragma unroll
    for (int i = 0; i < 8; i++) {
        int row = m0 + ty * 8 + i;
        float2 v0 = unpack2(acc[i][0]);
        float2 v1 = unpack2(acc[i][1]);
        float2 v2 = unpack2(acc[i][2]);
        float2 v3 = unpack2(acc[i][3]);
        float pel0 = v0.x * alv0.x + v0.y * alv0.y + v1.x * alv0.z + v1.y * alv0.w;
        float pel1 = v2.x * alv1.x + v2.y * alv1.y + v3.x * alv1.z + v3.y * alv1.w;
        float per0 = v0.x * arv0.x + v0.y * arv0.y + v1.x * arv0.z + v1.y * arv0.w;
        float per1 = v2.x * arv1.x + v2.y * arv1.y + v3.x * arv1.z + v3.y * arv1.w;
#pragma unroll
        for (int off = 8; off; off >>= 1) {
            pel0 += __shfl_down_sync(0xffffffffu, pel0, off, 16);
            pel1 += __shfl_down_sync(0xffffffffu, pel1, off, 16);
            per0 += __shfl_down_sync(0xffffffffu, per0, off, 16);
            per1 += __shfl_down_sync(0xffffffffu, per1, off, 16);
        }
        if (row < nrows) {
            __half2 ha = __floats2half2_rn(v0.x, v0.y);
            __half2 hb = __floats2half2_rn(v1.x, v1.y);
            __half2 hc = __floats2half2_rn(v2.x, v2.y);
            __half2 hd = __floats2half2_rn(v3.x, v3.y);
            uint2 s0, s1;
            s0.x = *(unsigned int*)&ha; s0.y = *(unsigned int*)&hb;
            s1.x = *(unsigned int*)&hc; s1.y = *(unsigned int*)&hd;
            *(uint2*)&fout[(size_t)row * Fd + tx * 4] = s0;
            *(uint2*)&fout[(size_t)row * Fd + 64 + tx * 4] = s1;
            if (tx == 0) {
                el[row * NH + 0] = pel0;
                el[row * NH + 1] = pel1;
                er[row * NH + 0] = per0;
                er[row * NH + 1] = per1;
            }
        }
    }
}

// ---------------- batched CSR build (4 graphs) -------------------------------
// hist: count + record within-bucket rank (coalesced write)
__global__ void __launch_bounds__(256) hist4_k(const int* __restrict__ dA,
                                               const int* __restrict__ dB,
                                               int* __restrict__ cnt,
                                               int* __restrict__ rank) {
    long long e = (long long)blockIdx.x * blockDim.x + threadIdx.x;
    if (e >= 4LL * Ee) return;
    int g = (int)(e / Ee);
    int i = (int)(e - (long long)g * Ee);
    const int* d = (g < 2) ? (dA + (size_t)g * Ee) : (dB + (size_t)(g - 2) * Ee);
    int rk = atomicAdd(&cnt[g * Nn + d[i]], 1);
    rank[(size_t)g * Ee + i] = rk;
}

__global__ void __launch_bounds__(1024) scanA_k(int* __restrict__ cnt,
                                                int* __restrict__ part) {
    __shared__ int sm[1024];
    int g = blockIdx.y;
    int i = blockIdx.x * 1024 + threadIdx.x;
    int v = (i < Nn) ? cnt[g * Nn + i] : 0;
    sm[threadIdx.x] = v;
    __syncthreads();
#pragma unroll
    for (int off = 1; off < 1024; off <<= 1) {
        int t = (threadIdx.x >= off) ? sm[threadIdx.x - off] : 0;
        __syncthreads();
        sm[threadIdx.x] += t;
        __syncthreads();
    }
    int incl = sm[threadIdx.x];
    if (i < Nn) cnt[g * Nn + i] = incl - v;        // exclusive within block
    if (threadIdx.x == 1023) part[g * 64 + blockIdx.x] = incl;
}

__global__ void scanB_k(int* __restrict__ part) {
    if (threadIdx.x == 0) {
        int* p = part + blockIdx.x * 64;
        int acc = 0;
        for (int i = 0; i < NB_SCAN; i++) { int t = p[i]; p[i] = acc; acc += t; }
    }
}

__global__ void __launch_bounds__(1024) scanC_k(int* __restrict__ cnt,
                                                const int* __restrict__ part) {
    int g = blockIdx.y;
    int i = blockIdx.x * 1024 + threadIdx.x;
    if (i < Nn) cnt[g * Nn + i] += part[g * 64 + blockIdx.x];
}

// scatter (atomic-free): pos = exclusive_start[dst] + rank[e]
__global__ void __launch_bounds__(256) scat4_k(const int* __restrict__ sA,
                                               const int* __restrict__ dA,
                                               const int* __restrict__ sB,
                                               const int* __restrict__ dB,
                                               const int* __restrict__ ptr,
                                               const int* __restrict__ rank,
                                               int* __restrict__ csr) {
    long long e = (long long)blockIdx.x * blockDim.x + threadIdx.x;
    if (e >= 4LL * Ee) return;
    int g = (int)(e / Ee);
    int i = (int)(e - (long long)g * Ee);
    const int* s = (g < 2) ? (sA + (size_t)g * Ee) : (sB + (size_t)(g - 2) * Ee);
    const int* d = (g < 2) ? (dA + (size_t)g * Ee) : (dB + (size_t)(g - 2) * Ee);
    int v = d[i];
    int pos = __ldg(&ptr[g * Nn + v]) + __ldg(&rank[(size_t)g * Ee + i]);
    csr[(size_t)g * Ee + pos] = s[i];
}

// ---------------- fused gather + softmax-normalize + elu, both relations ----
__device__ __forceinline__ float eluf(float v) {
    return (v > 0.f) ? v : expm1f(v);
}

// per-relation accumulation, 2x unrolled dual chains; ptr holds exclusive starts
__device__ __forceinline__ void rel_acc(int v, int lane, int h,
                                        const int* __restrict__ p,
                                        const int* __restrict__ c,
                                        const __half* __restrict__ f,
                                        const float* __restrict__ el, float erh,
                                        float& ox, float& oy, float& oz,
                                        float& ow, float& os) {
    int beg = __ldg(&p[v]);
    int end = (v + 1 < Nn) ? __ldg(&p[v + 1]) : Ee;
    float ax = 0.f, ay = 0.f, az = 0.f, aw = 0.f, sa = 0.f;
    float bx = 0.f, by = 0.f, bz = 0.f, bw = 0.f, sb = 0.f;
    int e = beg;
    for (; e + 2 <= end; e += 2) {
        int u0 = __ldg(&c[e]);
        int u1 = __ldg(&c[e + 1]);
        float sc0 = __ldg(&el[u0 * NH + h]) + erh;
        float sc1 = __ldg(&el[u1 * NH + h]) + erh;
        sc0 = (sc0 > 0.f) ? sc0 : 0.2f * sc0;
        sc1 = (sc1 > 0.f) ? sc1 : 0.2f * sc1;
        float w0 = __expf(sc0);
        float w1 = __expf(sc1);
        uint2 q0 = __ldg((const uint2*)(f + (size_t)u0 * Fd + lane * 4));
        uint2 q1 = __ldg((const uint2*)(f + (size_t)u1 * Fd + lane * 4));
        float2 fa0 = __half22float2(*(__half2*)&q0.x);
        float2 fb0 = __half22float2(*(__half2*)&q0.y);
        float2 fa1 = __half22float2(*(__half2*)&q1.x);
        float2 fb1 = __half22float2(*(__half2*)&q1.y);
        sa += w0; sb += w1;
        ax += fa0.x * w0; ay += fa0.y * w0; az += fb0.x * w0; aw += fb0.y * w0;
        bx += fa1.x * w1; by += fa1.y * w1; bz += fb1.x * w1; bw += fb1.y * w1;
    }
    if (e < end) {
        int u0 = __ldg(&c[e]);
        float sc0 = __ldg(&el[u0 * NH + h]) + erh;
        sc0 = (sc0 > 0.f) ? sc0 : 0.2f * sc0;
        float w0 = __expf(sc0);
        uint2 q0 = __ldg((const uint2*)(f + (size_t)u0 * Fd + lane * 4));
        float2 fa0 = __half22float2(*(__half2*)&q0.x);
        float2 fb0 = __half22float2(*(__half2*)&q0.y);
        sa += w0;
        ax += fa0.x * w0; ay += fa0.y * w0; az += fb0.x * w0; aw += fb0.y * w0;
    }
    ox = ax + bx; oy = ay + by; oz = az + bz; ow = aw + bw; os = sa + sb;
}

__global__ void __launch_bounds__(256) gather_k(
    const int* __restrict__ p0, const int* __restrict__ c0,
    const __half* __restrict__ f0, const float* __restrict__ el0,
    const float* __restrict__ er0, const float* __restrict__ bb0,
    const int* __restrict__ p1, const int* __restrict__ c1,
    const __half* __restrict__ f1, const float* __restrict__ el1,
    const float* __restrict__ er1, const float* __restrict__ bb1,
    float* __restrict__ hout) {
    int v = (int)(((size_t)blockIdx.x * blockDim.x + threadIdx.x) >> 5);
    if (v >= Nn) return;
    int lane = threadIdx.x & 31;
    int h = lane >> 4;  // lanes 0-15: head 0 (cols 0-63), 16-31: head 1

    float ox, oy, oz, ow;
    {
        float ax, ay, az, aw, s;
        rel_acc(v, lane, h, p0, c0, f0, el0, __ldg(&er0[v * NH + h]),
                ax, ay, az, aw, s);
        float inv = (s > 0.f) ? 1.f / s : 0.f;
        float4 bv = *(const float4*)&bb0[lane * 4];
        ox = eluf(ax * inv + bv.x);
        oy = eluf(ay * inv + bv.y);
        oz = eluf(az * inv + bv.z);
        ow = eluf(aw * inv + bv.w);
    }
    {
        float ax, ay, az, aw, s;
        rel_acc(v, lane, h, p1, c1, f1, el1, __ldg(&er1[v * NH + h]),
                ax, ay, az, aw, s);
        float inv = (s > 0.f) ? 1.f / s : 0.f;
        float4 bv = *(const float4*)&bb1[lane * 4];
        ox += eluf(ax * inv + bv.x);
        oy += eluf(ay * inv + bv.y);
        oz += eluf(az * inv + bv.z);
        ow += eluf(aw * inv + bv.w);
    }
    *(float4*)&hout[(size_t)v * Fd + lane * 4] = make_float4(ox, oy, oz, ow);
}

// ---------------- launch ----------------
extern "C" void kernel_launch(void* const* d_in, const int* in_sizes, int n_in,
                              void* d_out, int out_size) {
    const float* x   = (const float*)d_in[0];
    const float* W0  = (const float*)d_in[1];
    const float* al0 = (const float*)d_in[2];
    const float* ar0 = (const float*)d_in[3];
    const float* b0  = (const float*)d_in[4];
    const float* W1  = (const float*)d_in[5];
    const float* al1 = (const float*)d_in[6];
    const float* ar1 = (const float*)d_in[7];
    const float* b1  = (const float*)d_in[8];
    const int* src0  = (const int*)d_in[9];
    const int* dst0  = (const int*)d_in[10];
    const int* src1  = (const int*)d_in[11];
    const int* dst1  = (const int*)d_in[12];
    float* out = (float*)d_out;

    __half *f0, *f1;
    float *h1, *el0, *er0, *el1, *er1;
    int *ptr, *csr, *rank, *part;
    cudaGetSymbolAddress((void**)&f0, g_f0);
    cudaGetSymbolAddress((void**)&f1, g_f1);
    cudaGetSymbolAddress((void**)&h1, g_h1);
    cudaGetSymbolAddress((void**)&el0, g_el0);
    cudaGetSymbolAddress((void**)&er0, g_er0);
    cudaGetSymbolAddress((void**)&el1, g_el1);
    cudaGetSymbolAddress((void**)&er1, g_er1);
    cudaGetSymbolAddress((void**)&ptr, g_ptr);
    cudaGetSymbolAddress((void**)&csr, g_csr);
    cudaGetSymbolAddress((void**)&rank, g_rank);
    cudaGetSymbolAddress((void**)&part, g_part);

    cudaFuncSetAttribute(gemm_scores_k, cudaFuncAttributeMaxDynamicSharedMemorySize,
                         GEMM_SMEM);

    // side stream + events for CSR-build / GEMM overlap (created once;
    // identical launched work every call)
    static cudaStream_t s_side = nullptr;
    static cudaEvent_t evRoot = nullptr, evCsr = nullptr;
    if (!s_side) {
        cudaStreamCreateWithFlags(&s_side, cudaStreamNonBlocking);
        cudaEventCreateWithFlags(&evRoot, cudaEventDisableTiming);
        cudaEventCreateWithFlags(&evCsr, cudaEventDisableTiming);
    }

    // ---- fork: CSR build for all 4 graphs on side stream ----
    cudaEventRecord(evRoot, 0);
    cudaStreamWaitEvent(s_side, evRoot, 0);

    const int NE4 = (int)((4LL * Ee + 255) / 256);
    cudaMemsetAsync(ptr, 0, 4 * (size_t)Nn * sizeof(int), s_side);
    hist4_k<<<NE4, 256, 0, s_side>>>(dst0, dst1, ptr, rank);
    dim3 sg(NB_SCAN, 4);
    scanA_k<<<sg, 1024, 0, s_side>>>(ptr, part);
    scanB_k<<<4, 32, 0, s_side>>>(part);
    scanC_k<<<sg, 1024, 0, s_side>>>(ptr, part);   // ptr = exclusive starts
    scat4_k<<<NE4, 256, 0, s_side>>>(src0, dst0, src1, dst1, ptr, rank, csr);
    cudaEventRecord(evCsr, s_side);

    // ---- main stream: layer-0 projection runs concurrently with CSR build ----
    dim3 gg((Nn + 127) / 128, 2);
    gemm_scores_k<<<gg, 256, GEMM_SMEM>>>(x, W0, al0, ar0, f0, f1,
                                          el0, er0, el1, er1, Nn);

    // ---- join, then gathers + layer 1 ----
    cudaStreamWaitEvent(0, evCsr, 0);
    gather_k<<<(Nn * 32 + 255) / 256, 256>>>(
        ptr + 0 * Nn, csr + (size_t)0 * Ee, f0, el0, er0, b0,
        ptr + 1 * Nn, csr + (size_t)1 * Ee, f1, el1, er1, b0 + Fd, h1);

    gemm_scores_k<<<gg, 256, GEMM_SMEM>>>(h1, W1, al1, ar1, f0, f1,
                                          el0, er0, el1, er1, Nn);
    gather_k<<<(Nn * 32 + 255) / 256, 256>>>(
        ptr + 2 * Nn, csr + (size_t)2 * Ee, f0, el0, er0, b1,
        ptr + 3 * Nn, csr + (size_t)3 * Ee, f1, el1, er1, b1 + Fd, out);
}

// round 15
// speedup vs baseline: 1.0008x; 1.0008x over previous
#include <cuda_runtime.h>
#include <cuda_fp16.h>
#include <cstdint>

#define Nn 50000
#define Ee 800000
#define Fd 128          // feature dim = H*OUT = 128
#define NH 2            // heads
#define NB_SCAN 49      // ceil(Nn/1024)

// ---------------- scratch (no allocations allowed) ----------------
__device__ __half g_f0[(size_t)Nn * Fd];  // projected feats (fp16), relation 0
__device__ __half g_f1[(size_t)Nn * Fd];  // projected feats (fp16), relation 1
__device__ float  g_h1[(size_t)Nn * Fd];  // layer-1 output
__device__ float  g_el0[(size_t)Nn * NH];
__device__ float  g_er0[(size_t)Nn * NH];
__device__ float  g_el1[(size_t)Nn * NH];
__device__ float  g_er1[(size_t)Nn * NH];
__device__ int    g_ptr[4][Nn];           // per-graph EXCLUSIVE rowptr starts
__device__ int    g_csr[4][Ee];           // per-graph src ids grouped by dst
__device__ int    g_rank[4][Ee];          // within-bucket rank per edge
__device__ int    g_part[4 * 64];         // scan block partials

// ---------------- packed f32x2 helpers (Blackwell FFMA2 path) ----------------
__device__ __forceinline__ unsigned long long pack2(float lo, float hi) {
    unsigned long long r;
    asm("mov.b64 %0, {%1, %2};" : "=l"(r) : "f"(lo), "f"(hi));
    return r;
}
__device__ __forceinline__ void fma2(unsigned long long& d, unsigned long long a,
                                     unsigned long long b) {
    asm("fma.rn.f32x2 %0, %1, %2, %0;" : "+l"(d) : "l"(a), "l"(b));
}
__device__ __forceinline__ float2 unpack2(unsigned long long v) {
    float2 r;
    asm("mov.b64 {%0, %1}, %2;" : "=f"(r.x), "=f"(r.y) : "l"(v));
    return r;
}

// ---------------- GEMM + fused scores: both relations in one launch ----------
#define GEMM_SMEM (128 * 132 * 4 + 128 * 128 * 4)

__global__ void __launch_bounds__(256) gemm_scores_k(
    const float* __restrict__ A, const float* __restrict__ W,
    const float* __restrict__ al, const float* __restrict__ ar,
    __half* __restrict__ fo0, __half* __restrict__ fo1,
    float* __restrict__ el0, float* __restrict__ er0,
    float* __restrict__ el1, float* __restrict__ er1, int nrows) {
    extern __shared__ float sm[];
    float* As = sm;               // [128][132] padded
    float* Bs = sm + 128 * 132;   // [128][128]
    const int r = blockIdx.y;
    const float* B = W + (size_t)r * Fd * Fd;
    __half* fout = r ? fo1 : fo0;
    float* el = r ? el1 : el0;
    float* er = r ? er1 : er0;
    const float* alr = al + r * Fd;
    const float* arr = ar + r * Fd;
    const int m0 = blockIdx.x * 128;
    const int tid = threadIdx.x;

#pragma unroll
    for (int it = 0; it < 16; it++) {
        int idx = tid + it * 256;       // float4 index, 0..4095
        int row = idx >> 5;
        int c4 = (idx & 31) << 2;
        float4 va = make_float4(0.f, 0.f, 0.f, 0.f);
        if (m0 + row < nrows) va = *(const float4*)&A[(size_t)(m0 + row) * Fd + c4];
        *(float4*)&As[row * 132 + c4] = va;
        *(float4*)&Bs[row * 128 + c4] = *(const float4*)&B[row * Fd + c4];
    }
    __syncthreads();

    const int ty = tid >> 4;   // rows ty*8..ty*8+7
    const int tx = tid & 15;   // cols tx*4 (head0) and 64+tx*4 (head1)

    unsigned long long acc[8][4];
#pragma unroll
    for (int i = 0; i < 8; i++)
#pragma unroll
        for (int j = 0; j < 4; j++) acc[i][j] = 0ull;

#pragma unroll 4
    for (int k = 0; k < 128; k++) {
        float4 b0 = *(const float4*)&Bs[k * 128 + tx * 4];
        float4 b1 = *(const float4*)&Bs[k * 128 + 64 + tx * 4];
        unsigned long long bp0 = pack2(b0.x, b0.y);
        unsigned long long bp1 = pack2(b0.z, b0.w);
        unsigned long long bp2 = pack2(b1.x, b1.y);
        unsigned long long bp3 = pack2(b1.z, b1.w);
#pragma unroll
        for (int i = 0; i < 8; i++) {
            float a = As[(ty * 8 + i) * 132 + k];
            unsigned long long ap = pack2(a, a);
            fma2(acc[i][0], ap, bp0);
            fma2(acc[i][1], ap, bp1);
            fma2(acc[i][2], ap, bp2);
            fma2(acc[i][3], ap, bp3);
        }
    }

    float4 alv0 = __ldg((const float4*)&alr[tx * 4]);
    float4 alv1 = __ldg((const float4*)&alr[64 + tx * 4]);
    float4 arv0 = __ldg((const float4*)&arr[tx * 4]);
    float4 arv1 = __ldg((const float4*)&arr[64 + tx * 4]);

#pragma unroll
    for (int i = 0; i < 8; i++) {
        int row = m0 + ty * 8 + i;
        float2 v0 = unpack2(acc[i][0]);
        float2 v1 = unpack2(acc[i][1]);
        float2 v2 = unpack2(acc[i][2]);
        float2 v3 = unpack2(acc[i][3]);
        float pel0 = v0.x * alv0.x + v0.y * alv0.y + v1.x * alv0.z + v1.y * alv0.w;
        float pel1 = v2.x * alv1.x + v2.y * alv1.y + v3.x * alv1.z + v3.y * alv1.w;
        float per0 = v0.x * arv0.x + v0.y * arv0.y + v1.x * arv0.z + v1.y * arv0.w;
        float per1 = v2.x * arv1.x + v2.y * arv1.y + v3.x * arv1.z + v3.y * arv1.w;
#pragma unroll
        for (int off = 8; off; off >>= 1) {
            pel0 += __shfl_down_sync(0xffffffffu, pel0, off, 16);
            pel1 += __shfl_down_sync(0xffffffffu, pel1, off, 16);
            per0 += __shfl_down_sync(0xffffffffu, per0, off, 16);
            per1 += __shfl_down_sync(0xffffffffu, per1, off, 16);
        }
        if (row < nrows) {
            __half2 ha = __floats2half2_rn(v0.x, v0.y);
            __half2 hb = __floats2half2_rn(v1.x, v1.y);
            __half2 hc = __floats2half2_rn(v2.x, v2.y);
            __half2 hd = __floats2half2_rn(v3.x, v3.y);
            uint2 s0, s1;
            s0.x = *(unsigned int*)&ha; s0.y = *(unsigned int*)&hb;
            s1.x = *(unsigned int*)&hc; s1.y = *(unsigned int*)&hd;
            *(uint2*)&fout[(size_t)row * Fd + tx * 4] = s0;
            *(uint2*)&fout[(size_t)row * Fd + 64 + tx * 4] = s1;
            if (tx == 0) {
                el[row * NH + 0] = pel0;
                el[row * NH + 1] = pel1;
                er[row * NH + 0] = per0;
                er[row * NH + 1] = per1;
            }
        }
    }
}

// ---------------- batched CSR build (4 graphs) -------------------------------
// hist: count + record within-bucket rank (coalesced write)
__global__ void __launch_bounds__(256) hist4_k(const int* __restrict__ dA,
                                               const int* __restrict__ dB,
                                               int* __restrict__ cnt,
                                               int* __restrict__ rank) {
    long long e = (long long)blockIdx.x * blockDim.x + threadIdx.x;
    if (e >= 4LL * Ee) return;
    int g = (int)(e / Ee);
    int i = (int)(e - (long long)g * Ee);
    const int* d = (g < 2) ? (dA + (size_t)g * Ee) : (dB + (size_t)(g - 2) * Ee);
    int rk = atomicAdd(&cnt[g * Nn + d[i]], 1);
    rank[(size_t)g * Ee + i] = rk;
}

__global__ void __launch_bounds__(1024) scanA_k(int* __restrict__ cnt,
                                                int* __restrict__ part) {
    __shared__ int sm[1024];
    int g = blockIdx.y;
    int i = blockIdx.x * 1024 + threadIdx.x;
    int v = (i < Nn) ? cnt[g * Nn + i] : 0;
    sm[threadIdx.x] = v;
    __syncthreads();
#pragma unroll
    for (int off = 1; off < 1024; off <<= 1) {
        int t = (threadIdx.x >= off) ? sm[threadIdx.x - off] : 0;
        __syncthreads();
        sm[threadIdx.x] += t;
        __syncthreads();
    }
    int incl = sm[threadIdx.x];
    if (i < Nn) cnt[g * Nn + i] = incl - v;        // exclusive within block
    if (threadIdx.x == 1023) part[g * 64 + blockIdx.x] = incl;
}

__global__ void scanB_k(int* __restrict__ part) {
    if (threadIdx.x == 0) {
        int* p = part + blockIdx.x * 64;
        int acc = 0;
        for (int i = 0; i < NB_SCAN; i++) { int t = p[i]; p[i] = acc; acc += t; }
    }
}

__global__ void __launch_bounds__(1024) scanC_k(int* __restrict__ cnt,
                                                const int* __restrict__ part) {
    int g = blockIdx.y;
    int i = blockIdx.x * 1024 + threadIdx.x;
    if (i < Nn) cnt[g * Nn + i] += part[g * 64 + blockIdx.x];
}

// scatter (atomic-free): pos = exclusive_start[dst] + rank[e]
__global__ void __launch_bounds__(256) scat4_k(const int* __restrict__ sA,
                                               const int* __restrict__ dA,
                                               const int* __restrict__ sB,
                                               const int* __restrict__ dB,
                                               const int* __restrict__ ptr,
                                               const int* __restrict__ rank,
                                               int* __restrict__ csr) {
    long long e = (long long)blockIdx.x * blockDim.x + threadIdx.x;
    if (e >= 4LL * Ee) return;
    int g = (int)(e / Ee);
    int i = (int)(e - (long long)g * Ee);
    const int* s = (g < 2) ? (sA + (size_t)g * Ee) : (sB + (size_t)(g - 2) * Ee);
    const int* d = (g < 2) ? (dA + (size_t)g * Ee) : (dB + (size_t)(g - 2) * Ee);
    int v = d[i];
    int pos = __ldg(&ptr[g * Nn + v]) + __ldg(&rank[(size_t)g * Ee + i]);
    csr[(size_t)g * Ee + pos] = s[i];
}

// ---------------- fused gather + softmax-normalize + elu, both relations ----
__device__ __forceinline__ float eluf(float v) {
    return (v > 0.f) ? v : expm1f(v);
}

// per-relation accumulation, 2x unrolled dual chains; ptr holds exclusive starts
__device__ __forceinline__ void rel_acc(int v, int lane, int h,
                                        const int* __restrict__ p,
                                        const int* __restrict__ c,
                                        const __half* __restrict__ f,
                                        const float* __restrict__ el, float erh,
                                        float& ox, float& oy, float& oz,
                                        float& ow, float& os) {
    int beg = __ldg(&p[v]);
    int end = (v + 1 < Nn) ? __ldg(&p[v + 1]) : Ee;
    float ax = 0.f, ay = 0.f, az = 0.f, aw = 0.f, sa = 0.f;
    float bx = 0.f, by = 0.f, bz = 0.f, bw = 0.f, sb = 0.f;
    int e = beg;
    for (; e + 2 <= end; e += 2) {
        int u0 = __ldg(&c[e]);
        int u1 = __ldg(&c[e + 1]);
        float sc0 = __ldg(&el[u0 * NH + h]) + erh;
        float sc1 = __ldg(&el[u1 * NH + h]) + erh;
        sc0 = (sc0 > 0.f) ? sc0 : 0.2f * sc0;
        sc1 = (sc1 > 0.f) ? sc1 : 0.2f * sc1;
        float w0 = __expf(sc0);
        float w1 = __expf(sc1);
        uint2 q0 = __ldg((const uint2*)(f + (size_t)u0 * Fd + lane * 4));
        uint2 q1 = __ldg((const uint2*)(f + (size_t)u1 * Fd + lane * 4));
        float2 fa0 = __half22float2(*(__half2*)&q0.x);
        float2 fb0 = __half22float2(*(__half2*)&q0.y);
        float2 fa1 = __half22float2(*(__half2*)&q1.x);
        float2 fb1 = __half22float2(*(__half2*)&q1.y);
        sa += w0; sb += w1;
        ax += fa0.x * w0; ay += fa0.y * w0; az += fb0.x * w0; aw += fb0.y * w0;
        bx += fa1.x * w1; by += fa1.y * w1; bz += fb1.x * w1; bw += fb1.y * w1;
    }
    if (e < end) {
        int u0 = __ldg(&c[e]);
        float sc0 = __ldg(&el[u0 * NH + h]) + erh;
        sc0 = (sc0 > 0.f) ? sc0 : 0.2f * sc0;
        float w0 = __expf(sc0);
        uint2 q0 = __ldg((const uint2*)(f + (size_t)u0 * Fd + lane * 4));
        float2 fa0 = __half22float2(*(__half2*)&q0.x);
        float2 fb0 = __half22float2(*(__half2*)&q0.y);
        sa += w0;
        ax += fa0.x * w0; ay += fa0.y * w0; az += fb0.x * w0; aw += fb0.y * w0;
    }
    ox = ax + bx; oy = ay + by; oz = az + bz; ow = aw + bw; os = sa + sb;
}

__global__ void __launch_bounds__(256) gather_k(
    const int* __restrict__ p0, const int* __restrict__ c0,
    const __half* __restrict__ f0, const float* __restrict__ el0,
    const float* __restrict__ er0, const float* __restrict__ bb0,
    const int* __restrict__ p1, const int* __restrict__ c1,
    const __half* __restrict__ f1, const float* __restrict__ el1,
    const float* __restrict__ er1, const float* __restrict__ bb1,
    float* __restrict__ hout) {
    int v = (int)(((size_t)blockIdx.x * blockDim.x + threadIdx.x) >> 5);
    if (v >= Nn) return;
    int lane = threadIdx.x & 31;
    int h = lane >> 4;  // lanes 0-15: head 0 (cols 0-63), 16-31: head 1

    float ox, oy, oz, ow;
    {
        float ax, ay, az, aw, s;
        rel_acc(v, lane, h, p0, c0, f0, el0, __ldg(&er0[v * NH + h]),
                ax, ay, az, aw, s);
        float inv = (s > 0.f) ? 1.f / s : 0.f;
        float4 bv = *(const float4*)&bb0[lane * 4];
        ox = eluf(ax * inv + bv.x);
        oy = eluf(ay * inv + bv.y);
        oz = eluf(az * inv + bv.z);
        ow = eluf(aw * inv + bv.w);
    }
    {
        float ax, ay, az, aw, s;
        rel_acc(v, lane, h, p1, c1, f1, el1, __ldg(&er1[v * NH + h]),
                ax, ay, az, aw, s);
        float inv = (s > 0.f) ? 1.f / s : 0.f;
        float4 bv = *(const float4*)&bb1[lane * 4];
        ox += eluf(ax * inv + bv.x);
        oy += eluf(ay * inv + bv.y);
        oz += eluf(az * inv + bv.z);
        ow += eluf(aw * inv + bv.w);
    }
    *(float4*)&hout[(size_t)v * Fd + lane * 4] = make_float4(ox, oy, oz, ow);
}

// ---------------- launch ----------------
extern "C" void kernel_launch(void* const* d_in, const int* in_sizes, int n_in,
                              void* d_out, int out_size) {
    const float* x   = (const float*)d_in[0];
    const float* W0  = (const float*)d_in[1];
    const float* al0 = (const float*)d_in[2];
    const float* ar0 = (const float*)d_in[3];
    const float* b0  = (const float*)d_in[4];
    const float* W1  = (const float*)d_in[5];
    const float* al1 = (const float*)d_in[6];
    const float* ar1 = (const float*)d_in[7];
    const float* b1  = (const float*)d_in[8];
    const int* src0  = (const int*)d_in[9];
    const int* dst0  = (const int*)d_in[10];
    const int* src1  = (const int*)d_in[11];
    const int* dst1  = (const int*)d_in[12];
    float* out = (float*)d_out;

    __half *f0, *f1;
    float *h1, *el0, *er0, *el1, *er1;
    int *ptr, *csr, *rank, *part;
    cudaGetSymbolAddress((void**)&f0, g_f0);
    cudaGetSymbolAddress((void**)&f1, g_f1);
    cudaGetSymbolAddress((void**)&h1, g_h1);
    cudaGetSymbolAddress((void**)&el0, g_el0);
    cudaGetSymbolAddress((void**)&er0, g_er0);
    cudaGetSymbolAddress((void**)&el1, g_el1);
    cudaGetSymbolAddress((void**)&er1, g_er1);
    cudaGetSymbolAddress((void**)&ptr, g_ptr);
    cudaGetSymbolAddress((void**)&csr, g_csr);
    cudaGetSymbolAddress((void**)&rank, g_rank);
    cudaGetSymbolAddress((void**)&part, g_part);

    cudaFuncSetAttribute(gemm_scores_k, cudaFuncAttributeMaxDynamicSharedMemorySize,
                         GEMM_SMEM);

    // side stream + events for CSR-build / GEMM overlap (created once;
    // identical launched work every call)
    static cudaStream_t s_side = nullptr;
    static cudaEvent_t evRoot = nullptr, evCsr = nullptr;
    if (!s_side) {
        cudaStreamCreateWithFlags(&s_side, cudaStreamNonBlocking);
        cudaEventCreateWithFlags(&evRoot, cudaEventDisableTiming);
        cudaEventCreateWithFlags(&evCsr, cudaEventDisableTiming);
    }

    // ---- fork: CSR build for all 4 graphs on side stream ----
    cudaEventRecord(evRoot, 0);
    cudaStreamWaitEvent(s_side, evRoot, 0);

    const int NE4 = (int)((4LL * Ee + 255) / 256);
    cudaMemsetAsync(ptr, 0, 4 * (size_t)Nn * sizeof(int), s_side);
    hist4_k<<<NE4, 256, 0, s_side>>>(dst0, dst1, ptr, rank);
    dim3 sg(NB_SCAN, 4);
    scanA_k<<<sg, 1024, 0, s_side>>>(ptr, part);
    scanB_k<<<4, 32, 0, s_side>>>(part);
    scanC_k<<<sg, 1024, 0, s_side>>>(ptr, part);   // ptr = exclusive starts
    scat4_k<<<NE4, 256, 0, s_side>>>(src0, dst0, src1, dst1, ptr, rank, csr);
    cudaEventRecord(evCsr, s_side);

    // ---- main stream: layer-0 projection runs concurrently with CSR build ----
    dim3 gg((Nn + 127) / 128, 2);
    gemm_scores_k<<<gg, 256, GEMM_SMEM>>>(x, W0, al0, ar0, f0, f1,
                                          el0, er0, el1, er1, Nn);

    // ---- join, then gathers + layer 1 ----
    cudaStreamWaitEvent(0, evCsr, 0);
    gather_k<<<(Nn * 32 + 255) / 256, 256>>>(
        ptr + 0 * Nn, csr + (size_t)0 * Ee, f0, el0, er0, b0,
        ptr + 1 * Nn, csr + (size_t)1 * Ee, f1, el1, er1, b0 + Fd, h1);

    gemm_scores_k<<<gg, 256, GEMM_SMEM>>>(h1, W1, al1, ar1, f0, f1,
                                          el0, er0, el1, er1, Nn);
    gather_k<<<(Nn * 32 + 255) / 256, 256>>>(
        ptr + 2 * Nn, csr + (size_t)2 * Ee, f0, el0, er0, b1,
        ptr + 3 * Nn, csr + (size_t)3 * Ee, f1, el1, er1, b1 + Fd, out);
}